// round 3
// baseline (speedup 1.0000x reference)
#include <cuda_runtime.h>

// RSI fused single pass, v3. out[c] = g/(g+l) over 13-wide window of
// positive/negative relative deltas (0 when l==0).
//
// R2 ncu: L1 76%, issue 72% -> shared/MIO instruction bound. This version:
// no input staging (p from LDG.128 directly), packed float2 (g,l) smem with
// 128-bit skewed conflict-free access, __fdividef, fused epilogue.

#define NROWS 2048
#define NCOLS 8192
#define TPB   256
#define ITEMS 8
#define TILE  (TPB * ITEMS)   // 2048 outputs per block
#define MAXW  64

// Skew for conflict-free 128-bit LDS/STS at the access patterns used here.
__device__ __forceinline__ int SK(int i) { return i + 2 * (i >> 4); }

template <int W>
__global__ __launch_bounds__(TPB) void rsi_v3(
    const float* __restrict__ in,
    float* __restrict__ out,
    int out_cols)
{
    constexpr int NP   = TILE + W - 1;                 // p values needed: 2060
    constexpr int SKSZ = NP + 2 * (NP >> 4) + 4;       // skewed float2 slots

    __shared__ __align__(16) float2 s_gl[SKSZ];

    const int row  = blockIdx.y;
    const int base = blockIdx.x * TILE;
    const int tid  = threadIdx.x;
    const float* rin = in + (size_t)row * NCOLS;

    // ---- p-phase: 4 p-values per thread per iter, straight from gmem ----
    #pragma unroll
    for (int v = 0; v < 2; ++v) {
        const int i0 = 4 * tid + v * (TILE / 2);       // 0..2044, mult of 4
        const float4 x4 = *(const float4*)(rin + base + i0);
        const int c5 = base + i0 + 4;
        const float x5 = (c5 < NCOLS) ? rin[c5] : 0.0f;

        float xs[5] = {x4.x, x4.y, x4.z, x4.w, x5};
        float2 gl[4];
        #pragma unroll
        for (int c = 0; c < 4; ++c) {
            const float prev = xs[c];
            const float p = (prev != 0.0f) ? __fdividef(xs[c + 1] - prev, prev) : 0.0f;
            gl[c].x = fmaxf(p, 0.0f);
            gl[c].y = fmaxf(-p, 0.0f);
        }
        // i0..i0+3 stay inside one 16-element skew group -> SK contiguous
        float4* dst = (float4*)&s_gl[SK(i0)];
        dst[0] = make_float4(gl[0].x, gl[0].y, gl[1].x, gl[1].y);
        dst[1] = make_float4(gl[2].x, gl[2].y, gl[3].x, gl[3].y);
    }
    // tail: W-1 extra p-values (clamped; never consumed by valid outputs
    // when clamping actually triggers)
    if (tid < W - 1) {
        const int i = TILE + tid;
        const int c0 = base + i;
        const float prev = (c0 < NCOLS)     ? rin[c0]     : 0.0f;
        const float cur  = (c0 + 1 < NCOLS) ? rin[c0 + 1] : 0.0f;
        const float p = (prev != 0.0f) ? __fdividef(cur - prev, prev) : 0.0f;
        s_gl[SK(i)] = make_float2(fmaxf(p, 0.0f), fmaxf(-p, 0.0f));
    }
    __syncthreads();

    // ---- 8 sliding windows per thread via local prefix sums ----
    const int lo = tid * ITEMS;                        // even -> SK pairing ok
    float Pg = 0.0f, Pl = 0.0f;
    float qg[ITEMS], ql[ITEMS];
    float ov[ITEMS];

    #pragma unroll
    for (int jj = 0; jj < (ITEMS + W - 1 + 1) / 2; ++jj) {   // 10 paired iters
        const float4 v4 = *(const float4*)&s_gl[SK(lo + 2 * jj)];
        #pragma unroll
        for (int h = 0; h < 2; ++h) {
            const int j = 2 * jj + h;
            if (j < ITEMS + W - 1) {
                if (j < ITEMS) { qg[j] = Pg; ql[j] = Pl; }
                Pg += (h == 0) ? v4.x : v4.z;
                Pl += (h == 0) ? v4.y : v4.w;
                if (j >= W - 1) {
                    const int k = j - (W - 1);
                    const float g = Pg - qg[k];
                    const float l = Pl - ql[k];
                    ov[k] = (l != 0.0f) ? __fdividef(g, g + l) : 0.0f;
                }
            }
        }
    }

    // ---- store ----
    const int c0 = base + lo;
    float* rout = out + (size_t)row * out_cols + c0;
    if (c0 + ITEMS <= out_cols) {
        #pragma unroll
        for (int k = 0; k < ITEMS; ++k) rout[k] = ov[k];
    } else {
        #pragma unroll
        for (int k = 0; k < ITEMS; ++k)
            if (c0 + k < out_cols) rout[k] = ov[k];
    }
}

// ---- Generic fallback for unexpected window sizes ----
__global__ __launch_bounds__(TPB) void rsi_generic(
    const float* __restrict__ in,
    float* __restrict__ out,
    int out_cols, int w)
{
    __shared__ float s_in[TPB + MAXW + 1];
    __shared__ float s_g [TPB + MAXW];
    __shared__ float s_l [TPB + MAXW];

    const int row  = blockIdx.y;
    const int base = blockIdx.x * TPB;
    const float* rin = in + (size_t)row * NCOLS;

    const int need_in = TPB + w + 1;
    for (int i = threadIdx.x; i < need_in; i += TPB) {
        const int col = base + i;
        s_in[i] = (col < NCOLS) ? rin[col] : 0.0f;
    }
    __syncthreads();

    const int need_p = TPB + w;
    for (int i = threadIdx.x; i < need_p; i += TPB) {
        const float prev = s_in[i];
        const float cur  = s_in[i + 1];
        const float p = (prev != 0.0f) ? (cur - prev) / prev : 0.0f;
        s_g[i] = fmaxf(p, 0.0f);
        s_l[i] = fmaxf(-p, 0.0f);
    }
    __syncthreads();

    const int c = base + threadIdx.x;
    if (c < out_cols) {
        float g = 0.0f, l = 0.0f;
        for (int j = 0; j < w; ++j) {
            g += s_g[threadIdx.x + j];
            l += s_l[threadIdx.x + j];
        }
        out[(size_t)row * out_cols + c] = (l != 0.0f) ? g / (g + l) : 0.0f;
    }
}

extern "C" void kernel_launch(void* const* d_in, const int* in_sizes, int n_in,
                              void* d_out, int out_size)
{
    const float* in  = (const float*)d_in[0];
    float*       out = (float*)d_out;

    const int out_cols = out_size / NROWS;   // NCOLS - (window_size - 1)
    int w = NCOLS - out_cols;

    if (w == 13) {
        dim3 grid((out_cols + TILE - 1) / TILE, NROWS);
        rsi_v3<13><<<grid, TPB>>>(in, out, out_cols);
    } else {
        if (w < 1)    w = 1;
        if (w > MAXW) w = MAXW;
        dim3 grid((out_cols + TPB - 1) / TPB, NROWS);
        rsi_generic<<<grid, TPB>>>(in, out, out_cols, w);
    }
}

// round 4
// speedup vs baseline: 1.3961x; 1.3961x over previous
#include <cuda_runtime.h>

// RSI fused single pass, v4. out[c] = g/(g+l) over 13-wide window of
// positive/negative relative deltas (0 when no losses in window).
//
// R3 lesson: block barrier + few LDGs => latency bound. v4: warp-autonomous
// 256-output tiles (no __syncthreads), single signed-p smem array (gains and
// losses are mutually exclusive), stride-12 conflict-free warp-private smem,
// halo handled uniformly as virtual lanes 32/33.

#define NROWS 2048
#define NCOLS 8192
#define TPB   256
#define TILE  2048          // outputs per block (8 per thread)
#define MAXW  64
#define WSTRIDE 12          // smem floats per source lane (8 data + 4 pad)
#define WREGION (WSTRIDE * 34)  // 33 source slots + pad, 16B-aligned (408*4B)

__global__ __launch_bounds__(TPB) void rsi_v4(
    const float* __restrict__ in,
    float* __restrict__ out,
    int out_cols)
{
    __shared__ __align__(16) float s_p[8 * WREGION];

    const int tid  = threadIdx.x;
    const int lane = tid & 31;
    const int wrp  = tid >> 5;
    const int row  = blockIdx.y;
    // this warp's x/p/output base within the row
    const int base = blockIdx.x * TILE + wrp * 256;
    const float* rin = in + (size_t)row * NCOLS;
    float* pw = s_p + wrp * WREGION;

    // ---- load own 8 inputs + halo ----
    const int g0 = base + 8 * lane;                 // <= 8184: always in-row
    const float4 xa = *(const float4*)(rin + g0);
    const float4 xb = *(const float4*)(rin + g0 + 4);

    float xe = 0.0f;                                // warp-tail x values
    if (lane < 13) {
        const int ge = base + 256 + lane;
        xe = (ge < NCOLS) ? rin[ge] : 0.0f;
    }
    float x8 = __shfl_down_sync(0xffffffffu, xa.x, 1);
    if (lane == 31) {
        const int g8 = g0 + 8;
        x8 = (g8 < NCOLS) ? rin[g8] : 0.0f;
    }
    const float xen = __shfl_down_sync(0xffffffffu, xe, 1);

    // ---- own 8 p-values (registers) ----
    const float xs[9] = {xa.x, xa.y, xa.z, xa.w, xb.x, xb.y, xb.z, xb.w, x8};
    float p[8];
    #pragma unroll
    for (int c = 0; c < 8; ++c) {
        const float prev = xs[c];
        p[c] = (prev != 0.0f) ? __fdividef(xs[c + 1] - prev, prev) : 0.0f;
    }

    // ---- publish to warp-private smem (conflict-free stride-12 layout) ----
    *(float4*)(pw + WSTRIDE * lane)     = make_float4(p[0], p[1], p[2], p[3]);
    *(float4*)(pw + WSTRIDE * lane + 4) = make_float4(p[4], p[5], p[6], p[7]);
    if (lane < 12) {                                // halo p as lanes 32/33
        const float pe = (xe != 0.0f) ? __fdividef(xen - xe, xe) : 0.0f;
        const int slot = (lane < 8) ? (WSTRIDE * 32 + lane)
                                    : (WSTRIDE * 33 + (lane - 8));
        pw[slot] = pe;
    }
    __syncwarp();

    // ---- fetch 12 neighbor p-values (lanes 30/31 hit halo slots 32/33) ----
    const float4 n0 = *(const float4*)(pw + WSTRIDE * (lane + 1));
    const float4 n1 = *(const float4*)(pw + WSTRIDE * (lane + 1) + 4);
    const float4 n2 = *(const float4*)(pw + WSTRIDE * (lane + 2));

    const float v[20] = {p[0], p[1], p[2], p[3], p[4], p[5], p[6], p[7],
                         n0.x, n0.y, n0.z, n0.w, n1.x, n1.y, n1.z, n1.w,
                         n2.x, n2.y, n2.z, n2.w};

    // ---- 8 sliding 13-windows via local G/L prefixes + snapshots.
    // L-prefix is bitwise constant across zero losses -> exact l==0 branch.
    float G = 0.0f, L = 0.0f;
    float qg[8], ql[8], ov[8];
    #pragma unroll
    for (int j = 0; j < 20; ++j) {
        if (j < 8) { qg[j] = G; ql[j] = L; }
        G += fmaxf(v[j], 0.0f);
        L += fmaxf(-v[j], 0.0f);
        if (j >= 12) {
            const int k = j - 12;
            const float g = G - qg[k];
            const float l = L - ql[k];
            ov[k] = (l != 0.0f) ? __fdividef(g, g + l) : 0.0f;
        }
    }

    // ---- store ----
    float* rout = out + (size_t)row * out_cols;
    if (g0 + 8 <= out_cols) {
        #pragma unroll
        for (int k = 0; k < 8; ++k) rout[g0 + k] = ov[k];
    } else {
        #pragma unroll
        for (int k = 0; k < 8; ++k)
            if (g0 + k < out_cols) rout[g0 + k] = ov[k];
    }
}

// ---- Generic fallback for unexpected window sizes ----
__global__ __launch_bounds__(TPB) void rsi_generic(
    const float* __restrict__ in,
    float* __restrict__ out,
    int out_cols, int w)
{
    __shared__ float s_in[TPB + MAXW + 1];
    __shared__ float s_g [TPB + MAXW];
    __shared__ float s_l [TPB + MAXW];

    const int row  = blockIdx.y;
    const int base = blockIdx.x * TPB;
    const float* rin = in + (size_t)row * NCOLS;

    const int need_in = TPB + w + 1;
    for (int i = threadIdx.x; i < need_in; i += TPB) {
        const int col = base + i;
        s_in[i] = (col < NCOLS) ? rin[col] : 0.0f;
    }
    __syncthreads();

    const int need_p = TPB + w;
    for (int i = threadIdx.x; i < need_p; i += TPB) {
        const float prev = s_in[i];
        const float cur  = s_in[i + 1];
        const float p = (prev != 0.0f) ? (cur - prev) / prev : 0.0f;
        s_g[i] = fmaxf(p, 0.0f);
        s_l[i] = fmaxf(-p, 0.0f);
    }
    __syncthreads();

    const int c = base + threadIdx.x;
    if (c < out_cols) {
        float g = 0.0f, l = 0.0f;
        for (int j = 0; j < w; ++j) {
            g += s_g[threadIdx.x + j];
            l += s_l[threadIdx.x + j];
        }
        out[(size_t)row * out_cols + c] = (l != 0.0f) ? g / (g + l) : 0.0f;
    }
}

extern "C" void kernel_launch(void* const* d_in, const int* in_sizes, int n_in,
                              void* d_out, int out_size)
{
    const float* in  = (const float*)d_in[0];
    float*       out = (float*)d_out;

    const int out_cols = out_size / NROWS;   // NCOLS - (window_size - 1)
    int w = NCOLS - out_cols;

    if (w == 13) {
        dim3 grid((out_cols + TILE - 1) / TILE, NROWS);
        rsi_v4<<<grid, TPB>>>(in, out, out_cols);
    } else {
        if (w < 1)    w = 1;
        if (w > MAXW) w = MAXW;
        dim3 grid((out_cols + TPB - 1) / TPB, NROWS);
        rsi_generic<<<grid, TPB>>>(in, out, out_cols, w);
    }
}

// round 5
// speedup vs baseline: 1.7954x; 1.2860x over previous
#include <cuda_runtime.h>

// RSI fused single pass, v5. out[c] = g/(g+l) over 13-wide window of
// positive/negative relative deltas (0 when no losses in window).
//
// v4 post-mortem: stores were 70% of L1 wavefronts (stride-8 scalar STG =
// 8 lines/instr; STG.128 impossible since out_cols=8179 is odd => rows are
// 4B-misaligned). v5 adds an in-warp smem transpose so stores are coalesced
// (lane-consecutive scalar STG). Rest of v4 (warp-autonomous tiles, register
// p-values, conflict-free exchange, exact l==0) unchanged.

#define NROWS 2048
#define NCOLS 8192
#define TPB   256
#define TILE  2048          // outputs per block (8 per thread)
#define MAXW  64
#define WSTRIDE 12          // smem floats per source lane (8 data + 4 pad)
#define WREGION (WSTRIDE * 34)  // 408 floats per warp (>= 288 for transpose)

__global__ __launch_bounds__(TPB) void rsi_v5(
    const float* __restrict__ in,
    float* __restrict__ out,
    int out_cols)
{
    __shared__ __align__(16) float s_p[8 * WREGION];

    const int tid  = threadIdx.x;
    const int lane = tid & 31;
    const int wrp  = tid >> 5;
    const int row  = blockIdx.y;
    const int base = blockIdx.x * TILE + wrp * 256;   // warp's first column
    const float* rin = in + (size_t)row * NCOLS;
    float* pw = s_p + wrp * WREGION;

    // ---- load own 8 inputs + halo ----
    const int g0 = base + 8 * lane;                   // <= 8184: in-row
    const float4 xa = *(const float4*)(rin + g0);
    const float4 xb = *(const float4*)(rin + g0 + 4);

    float xe = 0.0f;                                  // warp-tail x values
    if (lane < 13) {
        const int ge = base + 256 + lane;
        xe = (ge < NCOLS) ? rin[ge] : 0.0f;
    }
    float x8 = __shfl_down_sync(0xffffffffu, xa.x, 1);
    if (lane == 31) {
        const int g8 = g0 + 8;
        x8 = (g8 < NCOLS) ? rin[g8] : 0.0f;
    }
    const float xen = __shfl_down_sync(0xffffffffu, xe, 1);

    // ---- own 8 p-values (registers) ----
    const float xs[9] = {xa.x, xa.y, xa.z, xa.w, xb.x, xb.y, xb.z, xb.w, x8};
    float p[8];
    #pragma unroll
    for (int c = 0; c < 8; ++c) {
        const float prev = xs[c];
        p[c] = (prev != 0.0f) ? __fdividef(xs[c + 1] - prev, prev) : 0.0f;
    }

    // ---- publish to warp-private smem (conflict-free stride-12) ----
    *(float4*)(pw + WSTRIDE * lane)     = make_float4(p[0], p[1], p[2], p[3]);
    *(float4*)(pw + WSTRIDE * lane + 4) = make_float4(p[4], p[5], p[6], p[7]);
    if (lane < 12) {                                  // halo p as lanes 32/33
        const float pe = (xe != 0.0f) ? __fdividef(xen - xe, xe) : 0.0f;
        const int slot = (lane < 8) ? (WSTRIDE * 32 + lane)
                                    : (WSTRIDE * 33 + (lane - 8));
        pw[slot] = pe;
    }
    __syncwarp();

    // ---- fetch 12 neighbor p-values (lanes 30/31 hit halo slots 32/33) ----
    const float4 n0 = *(const float4*)(pw + WSTRIDE * (lane + 1));
    const float4 n1 = *(const float4*)(pw + WSTRIDE * (lane + 1) + 4);
    const float4 n2 = *(const float4*)(pw + WSTRIDE * (lane + 2));

    const float v[20] = {p[0], p[1], p[2], p[3], p[4], p[5], p[6], p[7],
                         n0.x, n0.y, n0.z, n0.w, n1.x, n1.y, n1.z, n1.w,
                         n2.x, n2.y, n2.z, n2.w};

    // ---- 8 sliding 13-windows via local G/L prefixes + snapshots.
    // L-prefix is bitwise constant across zero losses -> exact l==0 branch.
    float G = 0.0f, L = 0.0f;
    float qg[8], ql[8], ov[8];
    #pragma unroll
    for (int j = 0; j < 20; ++j) {
        if (j < 8) { qg[j] = G; ql[j] = L; }
        G += fmaxf(v[j], 0.0f);
        L += fmaxf(-v[j], 0.0f);
        if (j >= 12) {
            const int k = j - 12;
            const float g = G - qg[k];
            const float l = L - ql[k];
            ov[k] = (l != 0.0f) ? __fdividef(g, g + l) : 0.0f;
        }
    }

    // ---- in-warp transpose for coalesced stores ----
    __syncwarp();                                     // neighbor reads done
    #pragma unroll
    for (int k = 0; k < 8; ++k)
        pw[9 * lane + k] = ov[k];                     // gcd(9,32)=1: no conflicts
    __syncwarp();

    float* rout = out + (size_t)row * out_cols;
    #pragma unroll
    for (int k = 0; k < 8; ++k) {
        const int o = lane + 32 * k;                  // 0..255, lane-consecutive
        const float val = pw[9 * (o >> 3) + (o & 7)];
        const int col = base + o;
        if (col < out_cols) rout[col] = val;          // coalesced STG.32
    }
}

// ---- Generic fallback for unexpected window sizes ----
__global__ __launch_bounds__(TPB) void rsi_generic(
    const float* __restrict__ in,
    float* __restrict__ out,
    int out_cols, int w)
{
    __shared__ float s_in[TPB + MAXW + 1];
    __shared__ float s_g [TPB + MAXW];
    __shared__ float s_l [TPB + MAXW];

    const int row  = blockIdx.y;
    const int base = blockIdx.x * TPB;
    const float* rin = in + (size_t)row * NCOLS;

    const int need_in = TPB + w + 1;
    for (int i = threadIdx.x; i < need_in; i += TPB) {
        const int col = base + i;
        s_in[i] = (col < NCOLS) ? rin[col] : 0.0f;
    }
    __syncthreads();

    const int need_p = TPB + w;
    for (int i = threadIdx.x; i < need_p; i += TPB) {
        const float prev = s_in[i];
        const float cur  = s_in[i + 1];
        const float p = (prev != 0.0f) ? (cur - prev) / prev : 0.0f;
        s_g[i] = fmaxf(p, 0.0f);
        s_l[i] = fmaxf(-p, 0.0f);
    }
    __syncthreads();

    const int c = base + threadIdx.x;
    if (c < out_cols) {
        float g = 0.0f, l = 0.0f;
        for (int j = 0; j < w; ++j) {
            g += s_g[threadIdx.x + j];
            l += s_l[threadIdx.x + j];
        }
        out[(size_t)row * out_cols + c] = (l != 0.0f) ? g / (g + l) : 0.0f;
    }
}

extern "C" void kernel_launch(void* const* d_in, const int* in_sizes, int n_in,
                              void* d_out, int out_size)
{
    const float* in  = (const float*)d_in[0];
    float*       out = (float*)d_out;

    const int out_cols = out_size / NROWS;   // NCOLS - (window_size - 1)
    int w = NCOLS - out_cols;

    if (w == 13) {
        dim3 grid((out_cols + TILE - 1) / TILE, NROWS);
        rsi_v5<<<grid, TPB>>>(in, out, out_cols);
    } else {
        if (w < 1)    w = 1;
        if (w > MAXW) w = MAXW;
        dim3 grid((out_cols + TPB - 1) / TPB, NROWS);
        rsi_generic<<<grid, TPB>>>(in, out, out_cols, w);
    }
}

// round 6
// speedup vs baseline: 1.9652x; 1.0946x over previous
#include <cuda_runtime.h>

// RSI fused single pass, v6. out[c] = g/(g+l) over 13-wide window of
// positive/negative relative deltas (0 when no losses in window).
//
// R5 ncu: issue 81.5%, alu 53% -> instruction bound. v6: ITEMS=16 (halo,
// exchange, prefix warm-up amortize 2x), signed-S prefix (FMNMX halved, loss
// prefix kept exact for l==0), STS.128 transpose writer reusing the exchange
// slots, coalesced scalar STG readers.

#define NROWS  2048
#define NCOLS  8192
#define TPB    256
#define ITEMS  16
#define WTILE  (32 * ITEMS)      // 512 outputs per warp
#define TILE   (8 * WTILE)       // 4096 outputs per block
#define MAXW   64
#define SLOT   20                // smem floats per source lane (16 data + 4 pad)
#define WREGION (SLOT * 33)      // 32 lanes + halo slot

__global__ __launch_bounds__(TPB) void rsi_v6(
    const float* __restrict__ in,
    float* __restrict__ out,
    int out_cols)
{
    __shared__ __align__(16) float s_p[8 * WREGION];

    const int tid   = threadIdx.x;
    const int lane  = tid & 31;
    const int wrp   = tid >> 5;
    const int row   = blockIdx.y;
    const int wbase = blockIdx.x * TILE + wrp * WTILE;   // warp's first column
    const float* rin = in + (size_t)row * NCOLS;
    float* pw = s_p + wrp * WREGION;

    const bool edge = (wbase + WTILE) >= NCOLS;          // last warp of the row

    // ---- load own 16 inputs (always in-row: wbase+512 <= 8192) ----
    const int g0 = wbase + ITEMS * lane;
    const float4 xA = *(const float4*)(rin + g0);
    const float4 xB = *(const float4*)(rin + g0 + 4);
    const float4 xC = *(const float4*)(rin + g0 + 8);
    const float4 xD = *(const float4*)(rin + g0 + 12);

    // x[g0+16]: neighbor's first x via shuffle; lane 31 loads (guarded)
    float x16 = __shfl_down_sync(0xffffffffu, xA.x, 1);
    if (lane == 31)
        x16 = (!edge) ? rin[g0 + 16] : 0.0f;

    // halo x: lanes 0..12 load x[wbase+512+lane] (guarded on edge warp)
    float xe = 0.0f;
    if (lane < 13) {
        const int ge = wbase + WTILE + lane;
        xe = (!edge || ge < NCOLS) ? rin[ge] : 0.0f;
    }
    const float xen = __shfl_down_sync(0xffffffffu, xe, 1);

    // ---- own 16 p-values ----
    const float xs[17] = {xA.x, xA.y, xA.z, xA.w, xB.x, xB.y, xB.z, xB.w,
                          xC.x, xC.y, xC.z, xC.w, xD.x, xD.y, xD.z, xD.w, x16};
    float p[ITEMS];
    #pragma unroll
    for (int c = 0; c < ITEMS; ++c) {
        const float prev = xs[c];
        p[c] = (prev != 0.0f) ? __fdividef(xs[c + 1] - prev, prev) : 0.0f;
    }

    // ---- publish p to warp-private smem (stride-20, conflict-free STS.128) ----
    float* myslot = pw + SLOT * lane;
    *(float4*)(myslot)      = make_float4(p[0],  p[1],  p[2],  p[3]);
    *(float4*)(myslot + 4)  = make_float4(p[4],  p[5],  p[6],  p[7]);
    *(float4*)(myslot + 8)  = make_float4(p[8],  p[9],  p[10], p[11]);
    *(float4*)(myslot + 12) = make_float4(p[12], p[13], p[14], p[15]);
    if (lane < 12) {                                     // halo p -> slot 32
        const float pe = (xe != 0.0f) ? __fdividef(xen - xe, xe) : 0.0f;
        pw[SLOT * 32 + lane] = pe;
    }
    __syncwarp();

    // ---- fetch 12 neighbor p-values (lane 31 hits halo slot 32) ----
    const float* nb = pw + SLOT * (lane + 1);
    const float4 n0 = *(const float4*)(nb);
    const float4 n1 = *(const float4*)(nb + 4);
    const float4 n2 = *(const float4*)(nb + 8);
    __syncwarp();                                        // reads done before overwrite

    const float v[ITEMS + 12] = {
        p[0], p[1], p[2],  p[3],  p[4],  p[5],  p[6],  p[7],
        p[8], p[9], p[10], p[11], p[12], p[13], p[14], p[15],
        n0.x, n0.y, n0.z, n0.w, n1.x, n1.y, n1.z, n1.w, n2.x, n2.y, n2.z, n2.w};

    // ---- 16 sliding 13-windows: signed prefix S + exact loss prefix L.
    // L snapshot is bitwise unchanged across zero-loss steps -> exact l==0.
    float S = 0.0f, L = 0.0f;
    float qs[ITEMS], ql[ITEMS], ov4[4];
    #pragma unroll
    for (int j = 0; j < ITEMS + 12; ++j) {
        if (j < ITEMS) { qs[j] = S; ql[j] = L; }
        S += v[j];
        L += fmaxf(-v[j], 0.0f);
        if (j >= 12) {
            const int k = j - 12;
            const float l = L - ql[k];
            const float g = (S - qs[k]) + l;             // gains = signed sum + losses
            ov4[k & 3] = (l != 0.0f) ? __fdividef(g, g + l) : 0.0f;
            if ((k & 3) == 3)                            // own slots: p[] consumed,
                *(float4*)(myslot + (k - 3)) =           // neighbors done reading
                    make_float4(ov4[0], ov4[1], ov4[2], ov4[3]);
        }
    }
    __syncwarp();

    // ---- coalesced scalar stores from transposed smem ----
    float* rout = out + (size_t)row * out_cols;
    if (!edge && wbase + WTILE <= out_cols) {
        #pragma unroll
        for (int m = 0; m < ITEMS; ++m) {
            const int o = lane + 32 * m;
            rout[wbase + o] = pw[SLOT * (o >> 4) + (o & 15)];
        }
    } else {
        #pragma unroll
        for (int m = 0; m < ITEMS; ++m) {
            const int o = lane + 32 * m;
            const int col = wbase + o;
            if (col < out_cols)
                rout[col] = pw[SLOT * (o >> 4) + (o & 15)];
        }
    }
}

// ---- Generic fallback for unexpected window sizes ----
__global__ __launch_bounds__(TPB) void rsi_generic(
    const float* __restrict__ in,
    float* __restrict__ out,
    int out_cols, int w)
{
    __shared__ float s_in[TPB + MAXW + 1];
    __shared__ float s_g [TPB + MAXW];
    __shared__ float s_l [TPB + MAXW];

    const int row  = blockIdx.y;
    const int base = blockIdx.x * TPB;
    const float* rin = in + (size_t)row * NCOLS;

    const int need_in = TPB + w + 1;
    for (int i = threadIdx.x; i < need_in; i += TPB) {
        const int col = base + i;
        s_in[i] = (col < NCOLS) ? rin[col] : 0.0f;
    }
    __syncthreads();

    const int need_p = TPB + w;
    for (int i = threadIdx.x; i < need_p; i += TPB) {
        const float prev = s_in[i];
        const float cur  = s_in[i + 1];
        const float p = (prev != 0.0f) ? (cur - prev) / prev : 0.0f;
        s_g[i] = fmaxf(p, 0.0f);
        s_l[i] = fmaxf(-p, 0.0f);
    }
    __syncthreads();

    const int c = base + threadIdx.x;
    if (c < out_cols) {
        float g = 0.0f, l = 0.0f;
        for (int j = 0; j < w; ++j) {
            g += s_g[threadIdx.x + j];
            l += s_l[threadIdx.x + j];
        }
        out[(size_t)row * out_cols + c] = (l != 0.0f) ? g / (g + l) : 0.0f;
    }
}

extern "C" void kernel_launch(void* const* d_in, const int* in_sizes, int n_in,
                              void* d_out, int out_size)
{
    const float* in  = (const float*)d_in[0];
    float*       out = (float*)d_out;

    const int out_cols = out_size / NROWS;   // NCOLS - (window_size - 1)
    int w = NCOLS - out_cols;

    if (w == 13) {
        dim3 grid((out_cols + TILE - 1) / TILE, NROWS);
        rsi_v6<<<grid, TPB>>>(in, out, out_cols);
    } else {
        if (w < 1)    w = 1;
        if (w > MAXW) w = MAXW;
        dim3 grid((out_cols + TPB - 1) / TPB, NROWS);
        rsi_generic<<<grid, TPB>>>(in, out, out_cols, w);
    }
}